// round 3
// baseline (speedup 1.0000x reference)
#include <cuda_runtime.h>
#include <stdint.h>

#define NBINS   100
#define NCOPIES 8
#define THREADS 256
#define GRID    1184   // 148 SMs * 8 blocks of 256 thr

__device__ float        g_bmin[GRID];
__device__ float        g_bmax[GRID];
__device__ unsigned int g_hist[NBINS];   // zero-init at load; last block restores zero
__device__ unsigned int g_done;          // ticket counter; restored to 0 each run

__global__ void __launch_bounds__(THREADS) minmax_kernel(const float* __restrict__ x, int n) {
    int n4 = n >> 2;
    const float4* __restrict__ x4 = (const float4*)x;

    float mn =  3.402823466e+38f;
    float mx = -3.402823466e+38f;

    const int stride = GRID * THREADS;
    int i = blockIdx.x * THREADS + threadIdx.x;

    for (; i + 3 * stride < n4; i += 4 * stride) {
        float4 v0 = x4[i];
        float4 v1 = x4[i + stride];
        float4 v2 = x4[i + 2 * stride];
        float4 v3 = x4[i + 3 * stride];
        mn = fminf(mn, fminf(fminf(v0.x, v0.y), fminf(v0.z, v0.w)));
        mx = fmaxf(mx, fmaxf(fmaxf(v0.x, v0.y), fmaxf(v0.z, v0.w)));
        mn = fminf(mn, fminf(fminf(v1.x, v1.y), fminf(v1.z, v1.w)));
        mx = fmaxf(mx, fmaxf(fmaxf(v1.x, v1.y), fmaxf(v1.z, v1.w)));
        mn = fminf(mn, fminf(fminf(v2.x, v2.y), fminf(v2.z, v2.w)));
        mx = fmaxf(mx, fmaxf(fmaxf(v2.x, v2.y), fmaxf(v2.z, v2.w)));
        mn = fminf(mn, fminf(fminf(v3.x, v3.y), fminf(v3.z, v3.w)));
        mx = fmaxf(mx, fmaxf(fmaxf(v3.x, v3.y), fmaxf(v3.z, v3.w)));
    }
    for (; i < n4; i += stride) {
        float4 v = x4[i];
        mn = fminf(mn, fminf(fminf(v.x, v.y), fminf(v.z, v.w)));
        mx = fmaxf(mx, fmaxf(fmaxf(v.x, v.y), fmaxf(v.z, v.w)));
    }
    if (blockIdx.x == 0) {
        int base = n4 << 2;
        for (int j = base + threadIdx.x; j < n; j += THREADS) {
            float v = x[j];
            mn = fminf(mn, v);
            mx = fmaxf(mx, v);
        }
    }

    #pragma unroll
    for (int o = 16; o > 0; o >>= 1) {
        mn = fminf(mn, __shfl_xor_sync(0xFFFFFFFFu, mn, o));
        mx = fmaxf(mx, __shfl_xor_sync(0xFFFFFFFFu, mx, o));
    }
    __shared__ float smn[THREADS / 32];
    __shared__ float smx[THREADS / 32];
    int wid = threadIdx.x >> 5;
    int lid = threadIdx.x & 31;
    if (lid == 0) { smn[wid] = mn; smx[wid] = mx; }
    __syncthreads();
    if (wid == 0) {
        mn = (lid < THREADS / 32) ? smn[lid] :  3.402823466e+38f;
        mx = (lid < THREADS / 32) ? smx[lid] : -3.402823466e+38f;
        #pragma unroll
        for (int o = 4; o > 0; o >>= 1) {
            mn = fminf(mn, __shfl_xor_sync(0xFFFFFFFFu, mn, o));
            mx = fmaxf(mx, __shfl_xor_sync(0xFFFFFFFFu, mx, o));
        }
        if (lid == 0) {
            g_bmin[blockIdx.x] = mn;
            g_bmax[blockIdx.x] = mx;
        }
    }
}

// hmin is the true data min, so (x - hmin) >= 0 exactly; only the upper clamp
// is needed. Keep FADD+FMUL (not fused) to match reference rounding exactly.
__device__ __forceinline__ int bin_of(float x, float hmin, float scale) {
    float d = (x - hmin) * scale;
    int b = __float2int_rd(d);
    return min(b, NBINS - 1);
}

// Warp-aggregated shared atomic: lanes with equal bin elect lowest lane,
// which adds popc once. Cuts same-address serial phases and lowers the
// max-bank-load at the ATOMS from ~3.5 to ~3.
__device__ __forceinline__ void hist_add(unsigned int* my, int b, unsigned lane) {
    unsigned m = __match_any_sync(0xFFFFFFFFu, b);
    if ((m & ((1u << lane) - 1u)) == 0u) {          // lowest-set lane is leader
        atomicAdd(&my[b], __popc(m));
    }
}

__global__ void __launch_bounds__(THREADS) hist_kernel(const float* __restrict__ x, int n,
                                                       float* __restrict__ out) {
    __shared__ unsigned int sh[NCOPIES * NBINS];
    __shared__ float s_hmin, s_hmax;

    // ---- re-reduce per-block min/max from L2 (overlaps with smem zeroing) ----
    {
        float mn =  3.402823466e+38f;
        float mx = -3.402823466e+38f;
        for (int j = threadIdx.x; j < GRID; j += THREADS) {
            mn = fminf(mn, g_bmin[j]);
            mx = fmaxf(mx, g_bmax[j]);
        }
        #pragma unroll
        for (int o = 16; o > 0; o >>= 1) {
            mn = fminf(mn, __shfl_xor_sync(0xFFFFFFFFu, mn, o));
            mx = fmaxf(mx, __shfl_xor_sync(0xFFFFFFFFu, mx, o));
        }
        __shared__ float rmn[THREADS / 32], rmx[THREADS / 32];
        int wid = threadIdx.x >> 5;
        int lid = threadIdx.x & 31;
        if (lid == 0) { rmn[wid] = mn; rmx[wid] = mx; }
        for (int j = threadIdx.x; j < NCOPIES * NBINS; j += THREADS) sh[j] = 0u;
        __syncthreads();
        if (threadIdx.x == 0) {
            float fmn = rmn[0], fmx = rmx[0];
            #pragma unroll
            for (int w = 1; w < THREADS / 32; w++) {
                fmn = fminf(fmn, rmn[w]);
                fmx = fmaxf(fmx, rmx[w]);
            }
            if (fmx == fmn) fmx = fmn + 1.0f;   // degenerate-range guard
            s_hmin = fmn;
            s_hmax = fmx;
        }
        __syncthreads();
    }

    const float hmin  = s_hmin;
    const float scale = (float)NBINS / (s_hmax - hmin);
    const unsigned lane = threadIdx.x & 31u;

    unsigned int* my = sh + ((threadIdx.x >> 5) & (NCOPIES - 1)) * NBINS;

    int n4 = n >> 2;
    const float4* __restrict__ x4 = (const float4*)x;
    const int stride = GRID * THREADS;
    int i = blockIdx.x * THREADS + threadIdx.x;

    for (; i + 3 * stride < n4; i += 4 * stride) {
        float4 v0 = x4[i];
        float4 v1 = x4[i + stride];
        float4 v2 = x4[i + 2 * stride];
        float4 v3 = x4[i + 3 * stride];
        hist_add(my, bin_of(v0.x, hmin, scale), lane);
        hist_add(my, bin_of(v0.y, hmin, scale), lane);
        hist_add(my, bin_of(v0.z, hmin, scale), lane);
        hist_add(my, bin_of(v0.w, hmin, scale), lane);
        hist_add(my, bin_of(v1.x, hmin, scale), lane);
        hist_add(my, bin_of(v1.y, hmin, scale), lane);
        hist_add(my, bin_of(v1.z, hmin, scale), lane);
        hist_add(my, bin_of(v1.w, hmin, scale), lane);
        hist_add(my, bin_of(v2.x, hmin, scale), lane);
        hist_add(my, bin_of(v2.y, hmin, scale), lane);
        hist_add(my, bin_of(v2.z, hmin, scale), lane);
        hist_add(my, bin_of(v2.w, hmin, scale), lane);
        hist_add(my, bin_of(v3.x, hmin, scale), lane);
        hist_add(my, bin_of(v3.y, hmin, scale), lane);
        hist_add(my, bin_of(v3.z, hmin, scale), lane);
        hist_add(my, bin_of(v3.w, hmin, scale), lane);
    }
    for (; i < n4; i += stride) {
        float4 v = x4[i];
        hist_add(my, bin_of(v.x, hmin, scale), lane);
        hist_add(my, bin_of(v.y, hmin, scale), lane);
        hist_add(my, bin_of(v.z, hmin, scale), lane);
        hist_add(my, bin_of(v.w, hmin, scale), lane);
    }
    if (blockIdx.x == 0) {
        int base = n4 << 2;
        for (int j = base + threadIdx.x; j < n; j += THREADS) {
            atomicAdd(&my[bin_of(x[j], hmin, scale)], 1u);
        }
    }
    __syncthreads();

    for (int b = threadIdx.x; b < NBINS; b += THREADS) {
        unsigned int s = 0;
        #pragma unroll
        for (int c = 0; c < NCOPIES; c++) s += sh[c * NBINS + b];
        if (s) atomicAdd(&g_hist[b], s);
    }

    // ---- fused finalize: last block converts g_hist -> out, restores zeros ----
    __threadfence();
    __syncthreads();
    __shared__ unsigned int s_ticket;
    if (threadIdx.x == 0) s_ticket = atomicAdd(&g_done, 1u);
    __syncthreads();
    if (s_ticket == GRID - 1) {
        __threadfence();
        for (int b = threadIdx.x; b < NBINS; b += THREADS) {
            out[b] = (float)g_hist[b];
            g_hist[b] = 0u;
        }
        if (threadIdx.x == 0) g_done = 0u;
    }
}

extern "C" void kernel_launch(void* const* d_in, const int* in_sizes, int n_in,
                              void* d_out, int out_size) {
    const float* x = (const float*)d_in[0];
    int n = in_sizes[0];
    float* out = (float*)d_out;

    minmax_kernel<<<GRID, THREADS>>>(x, n);
    hist_kernel<<<GRID, THREADS>>>(x, n, out);
}

// round 4
// speedup vs baseline: 4.8461x; 4.8461x over previous
#include <cuda_runtime.h>
#include <stdint.h>

#define NBINS   100
#define NCOPIES 8            // bank-disjoint interleaved copies, selected by lane%8
#define THREADS 256
#define GRID    1184         // 148 SMs * 8 blocks of 256 thr

__device__ float        g_bmin[GRID];
__device__ float        g_bmax[GRID];
__device__ unsigned int g_hist[NBINS];   // zero-init at load; last block restores zero
__device__ unsigned int g_done;          // ticket counter; restored to 0 each run

__global__ void __launch_bounds__(THREADS) minmax_kernel(const float* __restrict__ x, int n) {
    int n4 = n >> 2;
    const float4* __restrict__ x4 = (const float4*)x;

    float mn =  3.402823466e+38f;
    float mx = -3.402823466e+38f;

    const int stride = GRID * THREADS;
    int i = blockIdx.x * THREADS + threadIdx.x;

    for (; i + 3 * stride < n4; i += 4 * stride) {
        float4 v0 = x4[i];
        float4 v1 = x4[i + stride];
        float4 v2 = x4[i + 2 * stride];
        float4 v3 = x4[i + 3 * stride];
        mn = fminf(mn, fminf(fminf(v0.x, v0.y), fminf(v0.z, v0.w)));
        mx = fmaxf(mx, fmaxf(fmaxf(v0.x, v0.y), fmaxf(v0.z, v0.w)));
        mn = fminf(mn, fminf(fminf(v1.x, v1.y), fminf(v1.z, v1.w)));
        mx = fmaxf(mx, fmaxf(fmaxf(v1.x, v1.y), fmaxf(v1.z, v1.w)));
        mn = fminf(mn, fminf(fminf(v2.x, v2.y), fminf(v2.z, v2.w)));
        mx = fmaxf(mx, fmaxf(fmaxf(v2.x, v2.y), fmaxf(v2.z, v2.w)));
        mn = fminf(mn, fminf(fminf(v3.x, v3.y), fminf(v3.z, v3.w)));
        mx = fmaxf(mx, fmaxf(fmaxf(v3.x, v3.y), fmaxf(v3.z, v3.w)));
    }
    for (; i < n4; i += stride) {
        float4 v = x4[i];
        mn = fminf(mn, fminf(fminf(v.x, v.y), fminf(v.z, v.w)));
        mx = fmaxf(mx, fmaxf(fmaxf(v.x, v.y), fmaxf(v.z, v.w)));
    }
    if (blockIdx.x == 0) {
        int base = n4 << 2;
        for (int j = base + threadIdx.x; j < n; j += THREADS) {
            float v = x[j];
            mn = fminf(mn, v);
            mx = fmaxf(mx, v);
        }
    }

    #pragma unroll
    for (int o = 16; o > 0; o >>= 1) {
        mn = fminf(mn, __shfl_xor_sync(0xFFFFFFFFu, mn, o));
        mx = fmaxf(mx, __shfl_xor_sync(0xFFFFFFFFu, mx, o));
    }
    __shared__ float smn[THREADS / 32];
    __shared__ float smx[THREADS / 32];
    int wid = threadIdx.x >> 5;
    int lid = threadIdx.x & 31;
    if (lid == 0) { smn[wid] = mn; smx[wid] = mx; }
    __syncthreads();
    if (wid == 0) {
        mn = (lid < THREADS / 32) ? smn[lid] :  3.402823466e+38f;
        mx = (lid < THREADS / 32) ? smx[lid] : -3.402823466e+38f;
        #pragma unroll
        for (int o = 4; o > 0; o >>= 1) {
            mn = fminf(mn, __shfl_xor_sync(0xFFFFFFFFu, mn, o));
            mx = fmaxf(mx, __shfl_xor_sync(0xFFFFFFFFu, mx, o));
        }
        if (lid == 0) {
            g_bmin[blockIdx.x] = mn;
            g_bmax[blockIdx.x] = mx;
        }
    }
}

// hmin is the true data min, so (x - hmin) >= 0 exactly; only the upper clamp
// is needed. Keep FADD+FMUL (not fused) to match reference rounding exactly.
__device__ __forceinline__ int bin_of(float x, float hmin, float scale) {
    float d = (x - hmin) * scale;
    int b = __float2int_rd(d);
    return min(b, NBINS - 1);
}

__global__ void __launch_bounds__(THREADS) hist_kernel(const float* __restrict__ x, int n,
                                                       float* __restrict__ out) {
    // Interleaved layout: slot for (bin b, copy c) = b*8 + c.
    // Copy c touches only banks == c (mod 8) -> the 8 copies partition the
    // 32 banks; each copy serves 4 lanes over 4 private banks.
    __shared__ unsigned int sh[NBINS * NCOPIES];
    __shared__ float s_hmin, s_hmax;

    // ---- re-reduce per-block min/max from L2 (overlaps with smem zeroing) ----
    {
        float mn =  3.402823466e+38f;
        float mx = -3.402823466e+38f;
        for (int j = threadIdx.x; j < GRID; j += THREADS) {
            mn = fminf(mn, g_bmin[j]);
            mx = fmaxf(mx, g_bmax[j]);
        }
        #pragma unroll
        for (int o = 16; o > 0; o >>= 1) {
            mn = fminf(mn, __shfl_xor_sync(0xFFFFFFFFu, mn, o));
            mx = fmaxf(mx, __shfl_xor_sync(0xFFFFFFFFu, mx, o));
        }
        __shared__ float rmn[THREADS / 32], rmx[THREADS / 32];
        int wid = threadIdx.x >> 5;
        int lid = threadIdx.x & 31;
        if (lid == 0) { rmn[wid] = mn; rmx[wid] = mx; }
        for (int j = threadIdx.x; j < NBINS * NCOPIES; j += THREADS) sh[j] = 0u;
        __syncthreads();
        if (threadIdx.x == 0) {
            float fmn = rmn[0], fmx = rmx[0];
            #pragma unroll
            for (int w = 1; w < THREADS / 32; w++) {
                fmn = fminf(fmn, rmn[w]);
                fmx = fmaxf(fmx, rmx[w]);
            }
            if (fmx == fmn) fmx = fmn + 1.0f;   // degenerate-range guard
            s_hmin = fmn;
            s_hmax = fmx;
        }
        __syncthreads();
    }

    const float hmin  = s_hmin;
    const float scale = (float)NBINS / (s_hmax - hmin);

    // per-lane copy offset: lane % 8
    unsigned int* my = sh + (threadIdx.x & (NCOPIES - 1));

    int n4 = n >> 2;
    const float4* __restrict__ x4 = (const float4*)x;
    const int stride = GRID * THREADS;
    int i = blockIdx.x * THREADS + threadIdx.x;

    for (; i + 3 * stride < n4; i += 4 * stride) {
        float4 v0 = x4[i];
        float4 v1 = x4[i + stride];
        float4 v2 = x4[i + 2 * stride];
        float4 v3 = x4[i + 3 * stride];
        atomicAdd(&my[bin_of(v0.x, hmin, scale) * NCOPIES], 1u);
        atomicAdd(&my[bin_of(v0.y, hmin, scale) * NCOPIES], 1u);
        atomicAdd(&my[bin_of(v0.z, hmin, scale) * NCOPIES], 1u);
        atomicAdd(&my[bin_of(v0.w, hmin, scale) * NCOPIES], 1u);
        atomicAdd(&my[bin_of(v1.x, hmin, scale) * NCOPIES], 1u);
        atomicAdd(&my[bin_of(v1.y, hmin, scale) * NCOPIES], 1u);
        atomicAdd(&my[bin_of(v1.z, hmin, scale) * NCOPIES], 1u);
        atomicAdd(&my[bin_of(v1.w, hmin, scale) * NCOPIES], 1u);
        atomicAdd(&my[bin_of(v2.x, hmin, scale) * NCOPIES], 1u);
        atomicAdd(&my[bin_of(v2.y, hmin, scale) * NCOPIES], 1u);
        atomicAdd(&my[bin_of(v2.z, hmin, scale) * NCOPIES], 1u);
        atomicAdd(&my[bin_of(v2.w, hmin, scale) * NCOPIES], 1u);
        atomicAdd(&my[bin_of(v3.x, hmin, scale) * NCOPIES], 1u);
        atomicAdd(&my[bin_of(v3.y, hmin, scale) * NCOPIES], 1u);
        atomicAdd(&my[bin_of(v3.z, hmin, scale) * NCOPIES], 1u);
        atomicAdd(&my[bin_of(v3.w, hmin, scale) * NCOPIES], 1u);
    }
    for (; i < n4; i += stride) {
        float4 v = x4[i];
        atomicAdd(&my[bin_of(v.x, hmin, scale) * NCOPIES], 1u);
        atomicAdd(&my[bin_of(v.y, hmin, scale) * NCOPIES], 1u);
        atomicAdd(&my[bin_of(v.z, hmin, scale) * NCOPIES], 1u);
        atomicAdd(&my[bin_of(v.w, hmin, scale) * NCOPIES], 1u);
    }
    if (blockIdx.x == 0) {
        int base = n4 << 2;
        for (int j = base + threadIdx.x; j < n; j += THREADS) {
            atomicAdd(&my[bin_of(x[j], hmin, scale) * NCOPIES], 1u);
        }
    }
    __syncthreads();

    // reduce the 8 interleaved copies, one global atomic per (block, bin)
    for (int b = threadIdx.x; b < NBINS; b += THREADS) {
        unsigned int s = 0;
        #pragma unroll
        for (int c = 0; c < NCOPIES; c++) s += sh[b * NCOPIES + c];
        if (s) atomicAdd(&g_hist[b], s);
    }

    // ---- fused finalize: last block converts g_hist -> out, restores zeros ----
    __threadfence();
    __syncthreads();
    __shared__ unsigned int s_ticket;
    if (threadIdx.x == 0) s_ticket = atomicAdd(&g_done, 1u);
    __syncthreads();
    if (s_ticket == GRID - 1) {
        __threadfence();
        for (int b = threadIdx.x; b < NBINS; b += THREADS) {
            out[b] = (float)g_hist[b];
            g_hist[b] = 0u;
        }
        if (threadIdx.x == 0) g_done = 0u;
    }
}

extern "C" void kernel_launch(void* const* d_in, const int* in_sizes, int n_in,
                              void* d_out, int out_size) {
    const float* x = (const float*)d_in[0];
    int n = in_sizes[0];
    float* out = (float*)d_out;

    minmax_kernel<<<GRID, THREADS>>>(x, n);
    hist_kernel<<<GRID, THREADS>>>(x, n, out);
}

// round 5
// speedup vs baseline: 5.4467x; 1.1239x over previous
#include <cuda_runtime.h>
#include <stdint.h>

#define NBINS   100
#define NCOPIES 8            // bank-disjoint interleaved copies, selected by lane%8
#define THREADS 256
#define GRID    1184         // 148 SMs * 8 blocks of 256 thr

__device__ float        g_bmin[GRID];
__device__ float        g_bmax[GRID];
__device__ unsigned int g_hist[NBINS];   // zero-init at load; last block restores zero
__device__ unsigned int g_done;          // ticket counter; restored to 0 each run

// Forward sweep: finishes with the array TAIL resident in L2 (hist reads it first).
__global__ void __launch_bounds__(THREADS) minmax_kernel(const float* __restrict__ x, int n) {
    int n4 = n >> 2;
    const float4* __restrict__ x4 = (const float4*)x;

    float mn =  3.402823466e+38f;
    float mx = -3.402823466e+38f;

    const int stride = GRID * THREADS;
    int i = blockIdx.x * THREADS + threadIdx.x;

    for (; i + 3 * stride < n4; i += 4 * stride) {
        float4 v0 = x4[i];
        float4 v1 = x4[i + stride];
        float4 v2 = x4[i + 2 * stride];
        float4 v3 = x4[i + 3 * stride];
        mn = fminf(mn, fminf(fminf(v0.x, v0.y), fminf(v0.z, v0.w)));
        mx = fmaxf(mx, fmaxf(fmaxf(v0.x, v0.y), fmaxf(v0.z, v0.w)));
        mn = fminf(mn, fminf(fminf(v1.x, v1.y), fminf(v1.z, v1.w)));
        mx = fmaxf(mx, fmaxf(fmaxf(v1.x, v1.y), fmaxf(v1.z, v1.w)));
        mn = fminf(mn, fminf(fminf(v2.x, v2.y), fminf(v2.z, v2.w)));
        mx = fmaxf(mx, fmaxf(fmaxf(v2.x, v2.y), fmaxf(v2.z, v2.w)));
        mn = fminf(mn, fminf(fminf(v3.x, v3.y), fminf(v3.z, v3.w)));
        mx = fmaxf(mx, fmaxf(fmaxf(v3.x, v3.y), fmaxf(v3.z, v3.w)));
    }
    for (; i < n4; i += stride) {
        float4 v = x4[i];
        mn = fminf(mn, fminf(fminf(v.x, v.y), fminf(v.z, v.w)));
        mx = fmaxf(mx, fmaxf(fmaxf(v.x, v.y), fmaxf(v.z, v.w)));
    }
    if (blockIdx.x == 0) {
        int base = n4 << 2;
        for (int j = base + threadIdx.x; j < n; j += THREADS) {
            float v = x[j];
            mn = fminf(mn, v);
            mx = fmaxf(mx, v);
        }
    }

    #pragma unroll
    for (int o = 16; o > 0; o >>= 1) {
        mn = fminf(mn, __shfl_xor_sync(0xFFFFFFFFu, mn, o));
        mx = fmaxf(mx, __shfl_xor_sync(0xFFFFFFFFu, mx, o));
    }
    __shared__ float smn[THREADS / 32];
    __shared__ float smx[THREADS / 32];
    int wid = threadIdx.x >> 5;
    int lid = threadIdx.x & 31;
    if (lid == 0) { smn[wid] = mn; smx[wid] = mx; }
    __syncthreads();
    if (wid == 0) {
        mn = (lid < THREADS / 32) ? smn[lid] :  3.402823466e+38f;
        mx = (lid < THREADS / 32) ? smx[lid] : -3.402823466e+38f;
        #pragma unroll
        for (int o = 4; o > 0; o >>= 1) {
            mn = fminf(mn, __shfl_xor_sync(0xFFFFFFFFu, mn, o));
            mx = fmaxf(mx, __shfl_xor_sync(0xFFFFFFFFu, mx, o));
        }
        if (lid == 0) {
            g_bmin[blockIdx.x] = mn;
            g_bmax[blockIdx.x] = mx;
        }
    }
}

// hmin is the true data min, so (x - hmin) >= 0 exactly; only the upper clamp
// is needed. Keep FADD+FMUL (not fused) to match reference rounding exactly.
__device__ __forceinline__ int bin_of(float x, float hmin, float scale) {
    float d = (x - hmin) * scale;
    int b = __float2int_rd(d);
    return min(b, NBINS - 1);
}

// Reverse sweep: reads the tail (hot in L2 from minmax) first, and finishes
// with the array HEAD resident in L2 for the NEXT replay's minmax.
__global__ void __launch_bounds__(THREADS) hist_kernel(const float* __restrict__ x, int n,
                                                       float* __restrict__ out) {
    __shared__ unsigned int sh[NBINS * NCOPIES];
    __shared__ float s_hmin, s_hmax;

    // ---- re-reduce per-block min/max from L2 (overlaps with smem zeroing) ----
    {
        float mn =  3.402823466e+38f;
        float mx = -3.402823466e+38f;
        for (int j = threadIdx.x; j < GRID; j += THREADS) {
            mn = fminf(mn, g_bmin[j]);
            mx = fmaxf(mx, g_bmax[j]);
        }
        #pragma unroll
        for (int o = 16; o > 0; o >>= 1) {
            mn = fminf(mn, __shfl_xor_sync(0xFFFFFFFFu, mn, o));
            mx = fmaxf(mx, __shfl_xor_sync(0xFFFFFFFFu, mx, o));
        }
        __shared__ float rmn[THREADS / 32], rmx[THREADS / 32];
        int wid = threadIdx.x >> 5;
        int lid = threadIdx.x & 31;
        if (lid == 0) { rmn[wid] = mn; rmx[wid] = mx; }
        for (int j = threadIdx.x; j < NBINS * NCOPIES; j += THREADS) sh[j] = 0u;
        __syncthreads();
        if (threadIdx.x == 0) {
            float fmn = rmn[0], fmx = rmx[0];
            #pragma unroll
            for (int w = 1; w < THREADS / 32; w++) {
                fmn = fminf(fmn, rmn[w]);
                fmx = fmaxf(fmx, rmx[w]);
            }
            if (fmx == fmn) fmx = fmn + 1.0f;   // degenerate-range guard
            s_hmin = fmn;
            s_hmax = fmx;
        }
        __syncthreads();
    }

    const float hmin  = s_hmin;
    const float scale = (float)NBINS / (s_hmax - hmin);

    // per-lane copy offset: lane % 8 (8 copies partition the 32 banks)
    unsigned int* my = sh + (threadIdx.x & (NCOPIES - 1));

    int n4 = n >> 2;
    const float4* __restrict__ x4 = (const float4*)x;
    const int stride = GRID * THREADS;

    // descending grid-stride: same index set as ascending, opposite temporal order
    int i = (n4 - 1) - (int)(blockIdx.x * THREADS + threadIdx.x);

    for (; i - 3 * stride >= 0; i -= 4 * stride) {
        float4 v0 = x4[i];
        float4 v1 = x4[i - stride];
        float4 v2 = x4[i - 2 * stride];
        float4 v3 = x4[i - 3 * stride];
        atomicAdd(&my[bin_of(v0.x, hmin, scale) * NCOPIES], 1u);
        atomicAdd(&my[bin_of(v0.y, hmin, scale) * NCOPIES], 1u);
        atomicAdd(&my[bin_of(v0.z, hmin, scale) * NCOPIES], 1u);
        atomicAdd(&my[bin_of(v0.w, hmin, scale) * NCOPIES], 1u);
        atomicAdd(&my[bin_of(v1.x, hmin, scale) * NCOPIES], 1u);
        atomicAdd(&my[bin_of(v1.y, hmin, scale) * NCOPIES], 1u);
        atomicAdd(&my[bin_of(v1.z, hmin, scale) * NCOPIES], 1u);
        atomicAdd(&my[bin_of(v1.w, hmin, scale) * NCOPIES], 1u);
        atomicAdd(&my[bin_of(v2.x, hmin, scale) * NCOPIES], 1u);
        atomicAdd(&my[bin_of(v2.y, hmin, scale) * NCOPIES], 1u);
        atomicAdd(&my[bin_of(v2.z, hmin, scale) * NCOPIES], 1u);
        atomicAdd(&my[bin_of(v2.w, hmin, scale) * NCOPIES], 1u);
        atomicAdd(&my[bin_of(v3.x, hmin, scale) * NCOPIES], 1u);
        atomicAdd(&my[bin_of(v3.y, hmin, scale) * NCOPIES], 1u);
        atomicAdd(&my[bin_of(v3.z, hmin, scale) * NCOPIES], 1u);
        atomicAdd(&my[bin_of(v3.w, hmin, scale) * NCOPIES], 1u);
    }
    for (; i >= 0; i -= stride) {
        float4 v = x4[i];
        atomicAdd(&my[bin_of(v.x, hmin, scale) * NCOPIES], 1u);
        atomicAdd(&my[bin_of(v.y, hmin, scale) * NCOPIES], 1u);
        atomicAdd(&my[bin_of(v.z, hmin, scale) * NCOPIES], 1u);
        atomicAdd(&my[bin_of(v.w, hmin, scale) * NCOPIES], 1u);
    }
    if (blockIdx.x == 0) {
        int base = n4 << 2;
        for (int j = base + threadIdx.x; j < n; j += THREADS) {
            atomicAdd(&my[bin_of(x[j], hmin, scale) * NCOPIES], 1u);
        }
    }
    __syncthreads();

    // reduce the 8 interleaved copies, one global atomic per (block, bin)
    for (int b = threadIdx.x; b < NBINS; b += THREADS) {
        unsigned int s = 0;
        #pragma unroll
        for (int c = 0; c < NCOPIES; c++) s += sh[b * NCOPIES + c];
        if (s) atomicAdd(&g_hist[b], s);
    }

    // ---- fused finalize: last block converts g_hist -> out, restores zeros ----
    __threadfence();
    __syncthreads();
    __shared__ unsigned int s_ticket;
    if (threadIdx.x == 0) s_ticket = atomicAdd(&g_done, 1u);
    __syncthreads();
    if (s_ticket == GRID - 1) {
        __threadfence();
        for (int b = threadIdx.x; b < NBINS; b += THREADS) {
            out[b] = (float)g_hist[b];
            g_hist[b] = 0u;
        }
        if (threadIdx.x == 0) g_done = 0u;
    }
}

extern "C" void kernel_launch(void* const* d_in, const int* in_sizes, int n_in,
                              void* d_out, int out_size) {
    const float* x = (const float*)d_in[0];
    int n = in_sizes[0];
    float* out = (float*)d_out;

    minmax_kernel<<<GRID, THREADS>>>(x, n);
    hist_kernel<<<GRID, THREADS>>>(x, n, out);
}